// round 5
// baseline (speedup 1.0000x reference)
#include <cuda_runtime.h>
#include <cuda_bf16.h>
#include <cstdint>

// Shapes (fixed)
#define TQDIM 4096
#define TKDIM 4096
#define DMODEL 2048
#define NHEADS 4
#define ROWS 8192  // B*T

__device__ float g_qI[ROWS * 256];
__device__ float g_kI[ROWS * 64];
__device__ float g_wI[ROWS * 4];

// ---------------------------------------------------------------------------
// helpers
// ---------------------------------------------------------------------------
__device__ __forceinline__ void split1(float v, __nv_bfloat16& h,
                                       __nv_bfloat16& l) {
  h = __float2bfloat16(v);
  l = __float2bfloat16(v - __bfloat162float(h));
}
__device__ __forceinline__ uint32_t pack2(__nv_bfloat16 a, __nv_bfloat16 b) {
  return (uint32_t)__bfloat16_as_ushort(a) |
         ((uint32_t)__bfloat16_as_ushort(b) << 16);
}
__device__ __forceinline__ void split_f4(float4 v, uint2& hi, uint2& lo) {
  __nv_bfloat16 h0, l0, h1, l1, h2, l2, h3, l3;
  split1(v.x, h0, l0); split1(v.y, h1, l1);
  split1(v.z, h2, l2); split1(v.w, h3, l3);
  hi.x = pack2(h0, h1); hi.y = pack2(h2, h3);
  lo.x = pack2(l0, l1); lo.y = pack2(l2, l3);
}

__device__ __forceinline__ void mma_bf16(float* c, const uint32_t* a,
                                         uint32_t b0, uint32_t b1) {
  asm volatile(
      "mma.sync.aligned.m16n8k16.row.col.f32.bf16.bf16.f32 "
      "{%0,%1,%2,%3}, {%4,%5,%6,%7}, {%8,%9}, {%0,%1,%2,%3};\n"
      : "+f"(c[0]), "+f"(c[1]), "+f"(c[2]), "+f"(c[3])
      : "r"(a[0]), "r"(a[1]), "r"(a[2]), "r"(a[3]), "r"(b0), "r"(b1));
}

__device__ __forceinline__ void ldmx4(uint32_t* r, const void* p) {
  uint32_t a = (uint32_t)__cvta_generic_to_shared(p);
  asm volatile(
      "ldmatrix.sync.aligned.m8n8.x4.shared.b16 {%0,%1,%2,%3}, [%4];"
      : "=r"(r[0]), "=r"(r[1]), "=r"(r[2]), "=r"(r[3])
      : "r"(a));
}

__device__ __forceinline__ void cp16(void* dst, const void* src) {
  uint32_t d = (uint32_t)__cvta_generic_to_shared(dst);
  asm volatile("cp.async.cg.shared.global [%0], [%1], 16;" :: "r"(d), "l"(src));
}
#define CP_COMMIT() asm volatile("cp.async.commit_group;" ::: "memory")
#define CP_WAIT(n) asm volatile("cp.async.wait_group %0;" :: "n"(n) : "memory")

// ---------------------------------------------------------------------------
// Projection kernel: C[M,N] = A[M,K] @ W[K,N]  (bf16x3 HMMA)
// CTA 128x64, 8 warps (warp 16x64), 2 CTAs/SM.
// cp.async 3-stage fp32 staging, K-chunk 32, convert->bf16 tiles, ldmatrix.
// blocks 0..255: q_I (N=256, 4 col tiles); 256..319: k_I (N=64).
// ---------------------------------------------------------------------------
#define PKC 32
#define PSP 40  // halves stride of bf16 tiles (20 words -> conflict-free ldmatrix)
#define P_AST(b) ((b) * 16384)               // 128x32 f32
#define P_WST(b) (49152 + (b) * 8192)        // 32x64 f32
#define P_AH 73728
#define P_AL 83968
#define P_BH 94208
#define P_BL 99328
#define PROJ_SMEM 104448

__global__ __launch_bounds__(256, 2) void proj_kernel(
    const float* __restrict__ xq, const float* __restrict__ xk,
    const float* __restrict__ Wq, const float* __restrict__ Wk,
    float* __restrict__ qI, float* __restrict__ kI) {
  extern __shared__ __align__(16) char smem[];
  const int bx = blockIdx.x;
  const bool isQ = bx < 256;
  const int Nld = isQ ? 256 : 64;
  const int m0 = isQ ? (bx >> 2) * 128 : (bx - 256) * 128;
  const int n0 = isQ ? (bx & 3) * 64 : 0;
  const float* A = isQ ? xq : xk;
  const float* Wm = isQ ? Wq : Wk;
  float* C = isQ ? qI : kI;

  const int tid = threadIdx.x, wid = tid >> 5, lane = tid & 31;
  const int g = lane >> 2, q4 = lane & 3;
  const int mw = wid * 16;

  __nv_bfloat16* Ah = (__nv_bfloat16*)(smem + P_AH);
  __nv_bfloat16* Al = (__nv_bfloat16*)(smem + P_AL);
  __nv_bfloat16* Bh = (__nv_bfloat16*)(smem + P_BH);
  __nv_bfloat16* Bl = (__nv_bfloat16*)(smem + P_BL);

  // ldmatrix lane->row/col (see fragment layout of m16n8k16)
  const int aRow = mw + (lane & 7) + (lane & 8);
  const int aCol = (lane & 16) ? 8 : 0;
  const int bRow = (lane & 7) + ((lane & 16) ? 8 : 0);
  const int bCol = (lane & 8) ? 8 : 0;

  auto issue = [&](int kc) {
    char* ast = smem + P_AST(kc % 3);
    char* wst = smem + P_WST(kc % 3);
#pragma unroll
    for (int l = 0; l < 4; l++) {
      int idx = tid + l * 256, m = idx >> 3, c = idx & 7;
      cp16(ast + (m * 32 + c * 4) * 4,
           A + (size_t)(m0 + m) * DMODEL + kc * PKC + c * 4);
    }
#pragma unroll
    for (int l = 0; l < 2; l++) {
      int idx = tid + l * 256, kk = idx >> 4, c = idx & 15;
      cp16(wst + (kk * 64 + c * 4) * 4,
           Wm + (size_t)(kc * PKC + kk) * Nld + n0 + c * 4);
    }
    CP_COMMIT();
  };

  issue(0);
  issue(1);

  float dot[8][4] = {};
  const int NKC = DMODEL / PKC;  // 64

  for (int kc = 0; kc < NKC; kc++) {
    if (kc + 1 < NKC) { CP_WAIT(1); } else { CP_WAIT(0); }
    __syncthreads();  // previous MMA done -> bf16 tiles reusable
    // convert (each thread converts exactly the bytes it cp.async'd)
    {
      const float* Ast = (const float*)(smem + P_AST(kc % 3));
      const float* Wst = (const float*)(smem + P_WST(kc % 3));
#pragma unroll
      for (int l = 0; l < 4; l++) {
        int idx = tid + l * 256, m = idx >> 3, c = idx & 7;
        float4 v = *(const float4*)(Ast + m * 32 + c * 4);
        uint2 hi, lo;
        split_f4(v, hi, lo);
        *(uint2*)(Ah + m * PSP + c * 4) = hi;
        *(uint2*)(Al + m * PSP + c * 4) = lo;
      }
#pragma unroll
      for (int l = 0; l < 2; l++) {
        int idx = tid + l * 256, kk = idx >> 4, c = idx & 15;
        float4 v = *(const float4*)(Wst + kk * 64 + c * 4);
        __nv_bfloat16 h, lo;
        split1(v.x, h, lo); Bh[(c*4+0)*PSP+kk]=h; Bl[(c*4+0)*PSP+kk]=lo;
        split1(v.y, h, lo); Bh[(c*4+1)*PSP+kk]=h; Bl[(c*4+1)*PSP+kk]=lo;
        split1(v.z, h, lo); Bh[(c*4+2)*PSP+kk]=h; Bl[(c*4+2)*PSP+kk]=lo;
        split1(v.w, h, lo); Bh[(c*4+3)*PSP+kk]=h; Bl[(c*4+3)*PSP+kk]=lo;
      }
    }
    if (kc + 2 < NKC) issue(kc + 2);
    __syncthreads();

#pragma unroll
    for (int ks = 0; ks < 2; ks++) {
      uint32_t ah[4], al[4];
      ldmx4(ah, Ah + aRow * PSP + ks * 16 + aCol);
      ldmx4(al, Al + aRow * PSP + ks * 16 + aCol);
#pragma unroll
      for (int p = 0; p < 4; p++) {
        uint32_t bh[4], bl[4];
        ldmx4(bh, Bh + (p * 16 + bRow) * PSP + ks * 16 + bCol);
        ldmx4(bl, Bl + (p * 16 + bRow) * PSP + ks * 16 + bCol);
        mma_bf16(dot[2 * p], ah, bh[0], bh[1]);
        mma_bf16(dot[2 * p], ah, bl[0], bl[1]);
        mma_bf16(dot[2 * p], al, bh[0], bh[1]);
        mma_bf16(dot[2 * p + 1], ah, bh[2], bh[3]);
        mma_bf16(dot[2 * p + 1], ah, bl[2], bl[3]);
        mma_bf16(dot[2 * p + 1], al, bh[2], bh[3]);
      }
    }
  }

  const int r0 = m0 + mw + g;
#pragma unroll
  for (int nf = 0; nf < 8; nf++) {
    int col = n0 + nf * 8 + q4 * 2;
    *(float2*)&C[(size_t)r0 * Nld + col] = make_float2(dot[nf][0], dot[nf][1]);
    *(float2*)&C[(size_t)(r0 + 8) * Nld + col] =
        make_float2(dot[nf][2], dot[nf][3]);
  }
}

// ---------------------------------------------------------------------------
// w_I = x_q @ Ww (N=4): one warp per row.
// ---------------------------------------------------------------------------
__global__ __launch_bounds__(128) void wproj_kernel(
    const float* __restrict__ x, const float* __restrict__ Ww,
    float* __restrict__ wI) {
  int row = blockIdx.x * 4 + (threadIdx.x >> 5);
  int lane = threadIdx.x & 31;
  const float* xr = x + (size_t)row * DMODEL;
  float a0 = 0.f, a1 = 0.f, a2 = 0.f, a3 = 0.f;
  for (int d = lane; d < DMODEL; d += 32) {
    float xv = xr[d];
    float4 w = *(const float4*)&Ww[d * 4];
    a0 = fmaf(xv, w.x, a0);
    a1 = fmaf(xv, w.y, a1);
    a2 = fmaf(xv, w.z, a2);
    a3 = fmaf(xv, w.w, a3);
  }
#pragma unroll
  for (int off = 16; off; off >>= 1) {
    a0 += __shfl_down_sync(0xffffffffu, a0, off);
    a1 += __shfl_down_sync(0xffffffffu, a1, off);
    a2 += __shfl_down_sync(0xffffffffu, a2, off);
    a3 += __shfl_down_sync(0xffffffffu, a3, off);
  }
  if (lane == 0) *(float4*)&wI[(size_t)row * 4] = make_float4(a0, a1, a2, a3);
}

// ---------------------------------------------------------------------------
// Main kernel: 128q x 128k tile, 8 warps (4x2), warp tile 32x64.
// cp.async double-buffered q-head staging; ldmatrix fragments; per head:
// dot (bf16x3) -> relu -> w-weighted accumulate.
// ---------------------------------------------------------------------------
#define MSP 72
#define M_QST(b) ((b) * 32768)               // 128x64 f32
#define M_AH 65536
#define M_AL (65536 + 18432)
#define M_BH (65536 + 36864)
#define M_BL (65536 + 55296)
#define M_WS (65536 + 73728)
#define MAIN_SMEM (65536 + 73728 + 2048)     // 141312

__global__ __launch_bounds__(256, 1) void main_mma_kernel(
    const float* __restrict__ qI, const float* __restrict__ kI,
    const float* __restrict__ wI, float* __restrict__ out) {
  extern __shared__ __align__(16) char smem[];
  __nv_bfloat16* Ah = (__nv_bfloat16*)(smem + M_AH);
  __nv_bfloat16* Al = (__nv_bfloat16*)(smem + M_AL);
  __nv_bfloat16* Bh = (__nv_bfloat16*)(smem + M_BH);
  __nv_bfloat16* Bl = (__nv_bfloat16*)(smem + M_BL);
  float* ws = (float*)(smem + M_WS);

  const int tid = threadIdx.x, wid = tid >> 5, lane = tid & 31;
  const int g = lane >> 2, q4 = lane & 3;
  const int mwarp = (wid >> 1) * 32, nwarp = (wid & 1) * 64;
  const int b = blockIdx.z, q0 = blockIdx.y * 128, k0 = blockIdx.x * 128;

  const int aRow = (lane & 7) + (lane & 8);
  const int aCol = (lane & 16) ? 8 : 0;
  const int bRow = (lane & 7) + ((lane & 16) ? 8 : 0);
  const int bCol = (lane & 8) ? 8 : 0;

  const float* qb = qI + (size_t)(b * TQDIM + q0) * 256;

  auto issue_q = [&](int h) {
    char* st = smem + M_QST(h & 1);
#pragma unroll
    for (int l = 0; l < 8; l++) {
      int idx = tid + l * 256, m = idx >> 4, c = idx & 15;
      cp16(st + (m * 64 + c * 4) * 4, qb + (size_t)m * 256 + h * 64 + c * 4);
    }
    CP_COMMIT();
  };

  // prologue: k tile (shared across heads) + ws
  {
    const float* kb = kI + (size_t)(b * TKDIM + k0) * 64;
#pragma unroll
    for (int l = 0; l < 8; l++) {
      int idx = tid + l * 256, m = idx >> 4, c = idx & 15;
      float4 v = *(const float4*)(kb + (size_t)m * 64 + c * 4);
      uint2 hi, lo;
      split_f4(v, hi, lo);
      *(uint2*)(Bh + m * MSP + c * 4) = hi;
      *(uint2*)(Bl + m * MSP + c * 4) = lo;
    }
  }
  if (tid < 128)
    *(float4*)&ws[tid * 4] =
        *(const float4*)&wI[(size_t)(b * TQDIM + q0 + tid) * 4];

  issue_q(0);

  float acc[2][8][4] = {};

  for (int h = 0; h < NHEADS; h++) {
    if (h + 1 < NHEADS) { issue_q(h + 1); CP_WAIT(1); } else { CP_WAIT(0); }
    __syncthreads();  // MMA h-1 done -> Ah/Al reusable
    {
      const float* Qst = (const float*)(smem + M_QST(h & 1));
#pragma unroll
      for (int l = 0; l < 8; l++) {
        int idx = tid + l * 256, m = idx >> 4, c = idx & 15;
        float4 v = *(const float4*)(Qst + m * 64 + c * 4);
        uint2 hi, lo;
        split_f4(v, hi, lo);
        *(uint2*)(Ah + m * MSP + c * 4) = hi;
        *(uint2*)(Al + m * MSP + c * 4) = lo;
      }
    }
    __syncthreads();

    float dot[2][8][4] = {};
#pragma unroll
    for (int ks = 0; ks < 4; ks++) {
      uint32_t ah[2][4], al[2][4];
#pragma unroll
      for (int mf = 0; mf < 2; mf++) {
        ldmx4(ah[mf], Ah + (mwarp + mf * 16 + aRow) * MSP + ks * 16 + aCol);
        ldmx4(al[mf], Al + (mwarp + mf * 16 + aRow) * MSP + ks * 16 + aCol);
      }
#pragma unroll
      for (int p = 0; p < 4; p++) {
        uint32_t bh[4], bl[4];
        ldmx4(bh, Bh + (nwarp + p * 16 + bRow) * MSP + ks * 16 + bCol);
        ldmx4(bl, Bl + (nwarp + p * 16 + bRow) * MSP + ks * 16 + bCol);
#pragma unroll
        for (int mf = 0; mf < 2; mf++) {
          mma_bf16(dot[mf][2 * p], ah[mf], bh[0], bh[1]);
          mma_bf16(dot[mf][2 * p], ah[mf], bl[0], bl[1]);
          mma_bf16(dot[mf][2 * p], al[mf], bh[0], bh[1]);
          mma_bf16(dot[mf][2 * p + 1], ah[mf], bh[2], bh[3]);
          mma_bf16(dot[mf][2 * p + 1], ah[mf], bl[2], bl[3]);
          mma_bf16(dot[mf][2 * p + 1], al[mf], bh[2], bh[3]);
        }
      }
    }
    // relu + weighted accumulate
#pragma unroll
    for (int mf = 0; mf < 2; mf++) {
      float wa = ws[(mwarp + mf * 16 + g) * 4 + h];
      float wb = ws[(mwarp + mf * 16 + g + 8) * 4 + h];
#pragma unroll
      for (int nf = 0; nf < 8; nf++) {
        acc[mf][nf][0] = fmaf(wa, fmaxf(dot[mf][nf][0], 0.f), acc[mf][nf][0]);
        acc[mf][nf][1] = fmaf(wa, fmaxf(dot[mf][nf][1], 0.f), acc[mf][nf][1]);
        acc[mf][nf][2] = fmaf(wb, fmaxf(dot[mf][nf][2], 0.f), acc[mf][nf][2]);
        acc[mf][nf][3] = fmaf(wb, fmaxf(dot[mf][nf][3], 0.f), acc[mf][nf][3]);
      }
    }
  }

  float* obase = out + (size_t)(b * TQDIM + q0) * TKDIM + k0;
#pragma unroll
  for (int mf = 0; mf < 2; mf++) {
    int r0 = mwarp + mf * 16 + g;
#pragma unroll
    for (int nf = 0; nf < 8; nf++) {
      int col = nwarp + nf * 8 + q4 * 2;
      *(float2*)&obase[(size_t)r0 * TKDIM + col] =
          make_float2(acc[mf][nf][0], acc[mf][nf][1]);
      *(float2*)&obase[(size_t)(r0 + 8) * TKDIM + col] =
          make_float2(acc[mf][nf][2], acc[mf][nf][3]);
    }
  }
}

// ---------------------------------------------------------------------------
extern "C" void kernel_launch(void* const* d_in, const int* in_sizes, int n_in,
                              void* d_out, int out_size) {
  const float* x_q = (const float*)d_in[0];
  const float* x_k = (const float*)d_in[1];
  const float* Wq = (const float*)d_in[2];
  const float* Ww = (const float*)d_in[3];
  const float* Wk = (const float*)d_in[4];
  float* out = (float*)d_out;

  float *qI, *kI, *wI;
  cudaGetSymbolAddress((void**)&qI, g_qI);
  cudaGetSymbolAddress((void**)&kI, g_kI);
  cudaGetSymbolAddress((void**)&wI, g_wI);

  cudaFuncSetAttribute(proj_kernel, cudaFuncAttributeMaxDynamicSharedMemorySize,
                       PROJ_SMEM);
  cudaFuncSetAttribute(main_mma_kernel,
                       cudaFuncAttributeMaxDynamicSharedMemorySize, MAIN_SMEM);

  proj_kernel<<<320, 256, PROJ_SMEM>>>(x_q, x_k, Wq, Wk, qI, kI);
  wproj_kernel<<<2048, 128>>>(x_q, Ww, wI);
  main_mma_kernel<<<dim3(TKDIM / 128, TQDIM / 128, 2), 256, MAIN_SMEM>>>(
      qI, kI, wI, out);
}

// round 6
// speedup vs baseline: 1.3417x; 1.3417x over previous
#include <cuda_runtime.h>
#include <cuda_bf16.h>
#include <cstdint>

// Shapes (fixed)
#define TQDIM 4096
#define TKDIM 4096
#define DMODEL 2048
#define NHEADS 4
#define ROWS 8192  // B*T

// Pre-split inputs (hi/lo bf16)
__device__ __nv_bfloat16 g_xqh[ROWS * DMODEL];
__device__ __nv_bfloat16 g_xql[ROWS * DMODEL];
__device__ __nv_bfloat16 g_xkh[ROWS * DMODEL];
__device__ __nv_bfloat16 g_xkl[ROWS * DMODEL];
__device__ __nv_bfloat16 g_Wth[320 * DMODEL];  // [n][k]; n<256: Wq col, n>=256: Wk col
__device__ __nv_bfloat16 g_Wtl[320 * DMODEL];
// Projection outputs (hi/lo bf16); q head-major [h][row][64]
__device__ __nv_bfloat16 g_qIh[NHEADS * ROWS * 64];
__device__ __nv_bfloat16 g_qIl[NHEADS * ROWS * 64];
__device__ __nv_bfloat16 g_kIh[ROWS * 64];
__device__ __nv_bfloat16 g_kIl[ROWS * 64];
__device__ float g_wI[ROWS * 4];

// ---------------------------------------------------------------------------
// helpers
// ---------------------------------------------------------------------------
__device__ __forceinline__ void split1(float v, __nv_bfloat16& h,
                                       __nv_bfloat16& l) {
  h = __float2bfloat16(v);
  l = __float2bfloat16(v - __bfloat162float(h));
}
__device__ __forceinline__ uint32_t pack2(__nv_bfloat16 a, __nv_bfloat16 b) {
  return (uint32_t)__bfloat16_as_ushort(a) |
         ((uint32_t)__bfloat16_as_ushort(b) << 16);
}
__device__ __forceinline__ void split_f4(float4 v, uint2& hi, uint2& lo) {
  __nv_bfloat16 h0, l0, h1, l1, h2, l2, h3, l3;
  split1(v.x, h0, l0); split1(v.y, h1, l1);
  split1(v.z, h2, l2); split1(v.w, h3, l3);
  hi.x = pack2(h0, h1); hi.y = pack2(h2, h3);
  lo.x = pack2(l0, l1); lo.y = pack2(l2, l3);
}

__device__ __forceinline__ void mma_bf16(float* c, const uint32_t* a,
                                         uint32_t b0, uint32_t b1) {
  asm volatile(
      "mma.sync.aligned.m16n8k16.row.col.f32.bf16.bf16.f32 "
      "{%0,%1,%2,%3}, {%4,%5,%6,%7}, {%8,%9}, {%0,%1,%2,%3};\n"
      : "+f"(c[0]), "+f"(c[1]), "+f"(c[2]), "+f"(c[3])
      : "r"(a[0]), "r"(a[1]), "r"(a[2]), "r"(a[3]), "r"(b0), "r"(b1));
}

__device__ __forceinline__ void ldmx4(uint32_t* r, const void* p) {
  uint32_t a = (uint32_t)__cvta_generic_to_shared(p);
  asm volatile(
      "ldmatrix.sync.aligned.m8n8.x4.shared.b16 {%0,%1,%2,%3}, [%4];"
      : "=r"(r[0]), "=r"(r[1]), "=r"(r[2]), "=r"(r[3])
      : "r"(a));
}

__device__ __forceinline__ void cp16(void* dst, const void* src) {
  uint32_t d = (uint32_t)__cvta_generic_to_shared(dst);
  asm volatile("cp.async.cg.shared.global [%0], [%1], 16;" :: "r"(d), "l"(src));
}
#define CP_COMMIT() asm volatile("cp.async.commit_group;" ::: "memory")
#define CP_WAIT(n) asm volatile("cp.async.wait_group %0;" :: "n"(n) : "memory")

// ---------------------------------------------------------------------------
// One-shot split: fp32 -> hi/lo bf16 (streaming)
// ---------------------------------------------------------------------------
__global__ __launch_bounds__(256) void convert_kernel(
    const float* __restrict__ x, __nv_bfloat16* __restrict__ xh,
    __nv_bfloat16* __restrict__ xl, int n4) {
  int i = blockIdx.x * blockDim.x + threadIdx.x;
  if (i < n4) {
    float4 v = ((const float4*)x)[i];
    uint2 hi, lo;
    split_f4(v, hi, lo);
    ((uint2*)xh)[i] = hi;
    ((uint2*)xl)[i] = lo;
  }
}

// W transpose+split: Wt[n][k] = W[k][n]
__global__ __launch_bounds__(256) void wt_kernel(
    const float* __restrict__ Wq, const float* __restrict__ Wk,
    __nv_bfloat16* __restrict__ Wth, __nv_bfloat16* __restrict__ Wtl) {
  int k = blockIdx.x * 256 + threadIdx.x;  // 0..2047
  int n = blockIdx.y;                      // 0..319
  float v = (n < 256) ? Wq[(size_t)k * 256 + n] : Wk[(size_t)k * 64 + (n - 256)];
  __nv_bfloat16 h, l;
  split1(v, h, l);
  Wth[(size_t)n * DMODEL + k] = h;
  Wtl[(size_t)n * DMODEL + k] = l;
}

// ---------------------------------------------------------------------------
// Projection: C = A @ W^T (A, Wt pre-split bf16). CTA 128x64, 8 warps
// (warp 16x64), 2 CTAs/SM, 2-stage cp.async, K-chunk 64, ldmatrix + bf16x3.
// blocks 0..255: q (head = bx&3); 256..319: k.
// Outputs written as hi/lo bf16 (q head-major).
// ---------------------------------------------------------------------------
#define PSP 72                 // padded row stride in halves
#define PAB (128 * PSP * 2)    // A subtile bytes: 18432
#define PBB (64 * PSP * 2)     // B subtile bytes: 9216
#define PSTG (2 * PAB + 2 * PBB)   // 55296
#define PROJ_SMEM (2 * PSTG)       // 110592

__global__ __launch_bounds__(256, 2) void proj_kernel(
    __nv_bfloat16* __restrict__ qIh, __nv_bfloat16* __restrict__ qIl,
    __nv_bfloat16* __restrict__ kIh, __nv_bfloat16* __restrict__ kIl) {
  extern __shared__ __align__(16) char smem[];
  const int bx = blockIdx.x;
  const bool isQ = bx < 256;
  const int m0 = isQ ? (bx >> 2) * 128 : (bx - 256) * 128;
  const int head = isQ ? (bx & 3) : 0;
  const int nb = isQ ? head * 64 : 256;  // Wt row base

  const __nv_bfloat16* Ahs = isQ ? g_xqh : g_xkh;
  const __nv_bfloat16* Als = isQ ? g_xql : g_xkl;

  const int tid = threadIdx.x, wid = tid >> 5, lane = tid & 31;
  const int g = lane >> 2, q4 = lane & 3;
  const int mw = wid * 16;

  const int aRow = mw + (lane & 7) + (lane & 8);
  const int aCol = (lane & 16) ? 8 : 0;
  const int bRow = (lane & 7) + ((lane & 16) ? 8 : 0);
  const int bCol = (lane & 8) ? 8 : 0;

  auto issue = [&](int kc) {
    char* st = smem + (kc & 1) * PSTG;
#pragma unroll
    for (int l = 0; l < 4; l++) {
      int idx = tid + l * 256, m = idx >> 3, c = idx & 7;
      size_t src = (size_t)(m0 + m) * DMODEL + kc * 64 + c * 8;
      cp16(st + m * 144 + c * 16, Ahs + src);
      cp16(st + PAB + m * 144 + c * 16, Als + src);
    }
#pragma unroll
    for (int l = 0; l < 2; l++) {
      int idx = tid + l * 256, n = idx >> 3, c = idx & 7;
      size_t src = (size_t)(nb + n) * DMODEL + kc * 64 + c * 8;
      cp16(st + 2 * PAB + n * 144 + c * 16, g_Wth + src);
      cp16(st + 2 * PAB + PBB + n * 144 + c * 16, g_Wtl + src);
    }
    CP_COMMIT();
  };

  issue(0);
  issue(1);

  float dot[8][4] = {};
  const int NKC = DMODEL / 64;  // 32

  for (int kc = 0; kc < NKC; kc++) {
    if (kc + 1 < NKC) { CP_WAIT(1); } else { CP_WAIT(0); }
    __syncthreads();
    const char* st = smem + (kc & 1) * PSTG;
    const __nv_bfloat16* Ah = (const __nv_bfloat16*)st;
    const __nv_bfloat16* Al = (const __nv_bfloat16*)(st + PAB);
    const __nv_bfloat16* Bh = (const __nv_bfloat16*)(st + 2 * PAB);
    const __nv_bfloat16* Bl = (const __nv_bfloat16*)(st + 2 * PAB + PBB);

#pragma unroll
    for (int ks = 0; ks < 4; ks++) {
      uint32_t ah[4], al[4];
      ldmx4(ah, Ah + aRow * PSP + ks * 16 + aCol);
      ldmx4(al, Al + aRow * PSP + ks * 16 + aCol);
#pragma unroll
      for (int p = 0; p < 4; p++) {
        uint32_t bh[4], bl[4];
        ldmx4(bh, Bh + (p * 16 + bRow) * PSP + ks * 16 + bCol);
        ldmx4(bl, Bl + (p * 16 + bRow) * PSP + ks * 16 + bCol);
        mma_bf16(dot[2 * p], ah, bh[0], bh[1]);
        mma_bf16(dot[2 * p], ah, bl[0], bl[1]);
        mma_bf16(dot[2 * p], al, bh[0], bh[1]);
        mma_bf16(dot[2 * p + 1], ah, bh[2], bh[3]);
        mma_bf16(dot[2 * p + 1], ah, bl[2], bl[3]);
        mma_bf16(dot[2 * p + 1], al, bh[2], bh[3]);
      }
    }
    __syncthreads();
    if (kc + 2 < NKC) issue(kc + 2);
  }

  // epilogue: split results to hi/lo, write
  __nv_bfloat16* Oh = isQ ? (qIh + ((size_t)head * ROWS + m0) * 64)
                          : (kIh + (size_t)m0 * 64);
  __nv_bfloat16* Ol = isQ ? (qIl + ((size_t)head * ROWS + m0) * 64)
                          : (kIl + (size_t)m0 * 64);
  const int rl = mw + g;
#pragma unroll
  for (int nf = 0; nf < 8; nf++) {
    int col = nf * 8 + q4 * 2;
    __nv_bfloat16 h0, l0, h1, l1;
    split1(dot[nf][0], h0, l0);
    split1(dot[nf][1], h1, l1);
    *(uint32_t*)(Oh + (size_t)rl * 64 + col) = pack2(h0, h1);
    *(uint32_t*)(Ol + (size_t)rl * 64 + col) = pack2(l0, l1);
    split1(dot[nf][2], h0, l0);
    split1(dot[nf][3], h1, l1);
    *(uint32_t*)(Oh + (size_t)(rl + 8) * 64 + col) = pack2(h0, h1);
    *(uint32_t*)(Ol + (size_t)(rl + 8) * 64 + col) = pack2(l0, l1);
  }
}

// ---------------------------------------------------------------------------
// w_I = x_q @ Ww (N=4): one warp per row.
// ---------------------------------------------------------------------------
__global__ __launch_bounds__(128) void wproj_kernel(
    const float* __restrict__ x, const float* __restrict__ Ww,
    float* __restrict__ wI) {
  int row = blockIdx.x * 4 + (threadIdx.x >> 5);
  int lane = threadIdx.x & 31;
  const float* xr = x + (size_t)row * DMODEL;
  float a0 = 0.f, a1 = 0.f, a2 = 0.f, a3 = 0.f;
  for (int d = lane; d < DMODEL; d += 32) {
    float xv = xr[d];
    float4 w = *(const float4*)&Ww[d * 4];
    a0 = fmaf(xv, w.x, a0);
    a1 = fmaf(xv, w.y, a1);
    a2 = fmaf(xv, w.z, a2);
    a3 = fmaf(xv, w.w, a3);
  }
#pragma unroll
  for (int off = 16; off; off >>= 1) {
    a0 += __shfl_down_sync(0xffffffffu, a0, off);
    a1 += __shfl_down_sync(0xffffffffu, a1, off);
    a2 += __shfl_down_sync(0xffffffffu, a2, off);
    a3 += __shfl_down_sync(0xffffffffu, a3, off);
  }
  if (lane == 0) *(float4*)&wI[(size_t)row * 4] = make_float4(a0, a1, a2, a3);
}

// ---------------------------------------------------------------------------
// Main: 128q x 128k tile, 8 warps (4x2), warp 32x64. Pre-split bf16 inputs;
// A (q-head) double-buffered cp.async; per head: dot -> relu -> w-acc.
// ---------------------------------------------------------------------------
#define MSP 72
#define MAB (128 * MSP * 2)              // 18432
#define MAIN_SMEM (6 * MAB + 2048)       // 112640

__global__ __launch_bounds__(256, 1) void main_mma_kernel(
    const float* __restrict__ wI, float* __restrict__ out) {
  extern __shared__ __align__(16) char smem[];
  // A buf i: smem + i*2*MAB (hi), +MAB (lo); B: smem + 4*MAB (hi), 5*MAB (lo)
  float* ws = (float*)(smem + 6 * MAB);

  const int tid = threadIdx.x, wid = tid >> 5, lane = tid & 31;
  const int g = lane >> 2, q4 = lane & 3;
  const int mwarp = (wid >> 1) * 32, nwarp = (wid & 1) * 64;
  const int b = blockIdx.z, q0 = blockIdx.y * 128, k0 = blockIdx.x * 128;

  const int aRow = (lane & 7) + (lane & 8);
  const int aCol = (lane & 16) ? 8 : 0;
  const int bRow = (lane & 7) + ((lane & 16) ? 8 : 0);
  const int bCol = (lane & 8) ? 8 : 0;

  auto issueA = [&](int h) {
    char* st = smem + (h & 1) * 2 * MAB;
    size_t base = ((size_t)h * ROWS + b * TQDIM + q0) * 64;
#pragma unroll
    for (int l = 0; l < 4; l++) {
      int idx = tid + l * 256, m = idx >> 3, c = idx & 7;
      cp16(st + m * 144 + c * 16, g_qIh + base + (size_t)m * 64 + c * 8);
      cp16(st + MAB + m * 144 + c * 16, g_qIl + base + (size_t)m * 64 + c * 8);
    }
  };

  // prologue: group0 = B + A(0); group1 = A(1)
  {
    char* st = smem + 4 * MAB;
    size_t base = ((size_t)b * TKDIM + k0) * 64;
#pragma unroll
    for (int l = 0; l < 4; l++) {
      int idx = tid + l * 256, m = idx >> 3, c = idx & 7;
      cp16(st + m * 144 + c * 16, g_kIh + base + (size_t)m * 64 + c * 8);
      cp16(st + MAB + m * 144 + c * 16, g_kIl + base + (size_t)m * 64 + c * 8);
    }
  }
  issueA(0);
  CP_COMMIT();
  issueA(1);
  CP_COMMIT();
  if (tid < 128)
    *(float4*)&ws[tid * 4] =
        *(const float4*)&wI[(size_t)(b * TQDIM + q0 + tid) * 4];

  const __nv_bfloat16* Bh = (const __nv_bfloat16*)(smem + 4 * MAB);
  const __nv_bfloat16* Bl = (const __nv_bfloat16*)(smem + 5 * MAB);

  float acc[2][8][4] = {};

  for (int h = 0; h < NHEADS; h++) {
    if (h + 1 < NHEADS) { CP_WAIT(1); } else { CP_WAIT(0); }
    __syncthreads();
    const __nv_bfloat16* Ah =
        (const __nv_bfloat16*)(smem + (h & 1) * 2 * MAB);
    const __nv_bfloat16* Al = (const __nv_bfloat16*)((char*)Ah + MAB);

    float dot[2][8][4] = {};
#pragma unroll
    for (int ks = 0; ks < 4; ks++) {
      uint32_t ah[2][4], al[2][4];
#pragma unroll
      for (int mf = 0; mf < 2; mf++) {
        ldmx4(ah[mf], Ah + (mwarp + mf * 16 + aRow) * MSP + ks * 16 + aCol);
        ldmx4(al[mf], Al + (mwarp + mf * 16 + aRow) * MSP + ks * 16 + aCol);
      }
#pragma unroll
      for (int p = 0; p < 4; p++) {
        uint32_t bh[4], bl[4];
        ldmx4(bh, Bh + (nwarp + p * 16 + bRow) * MSP + ks * 16 + bCol);
        ldmx4(bl, Bl + (nwarp + p * 16 + bRow) * MSP + ks * 16 + bCol);
#pragma unroll
        for (int mf = 0; mf < 2; mf++) {
          mma_bf16(dot[mf][2 * p], ah[mf], bh[0], bh[1]);
          mma_bf16(dot[mf][2 * p], ah[mf], bl[0], bl[1]);
          mma_bf16(dot[mf][2 * p], al[mf], bh[0], bh[1]);
          mma_bf16(dot[mf][2 * p + 1], ah[mf], bh[2], bh[3]);
          mma_bf16(dot[mf][2 * p + 1], ah[mf], bl[2], bl[3]);
          mma_bf16(dot[mf][2 * p + 1], al[mf], bh[2], bh[3]);
        }
      }
    }
    // relu + weighted accumulate
#pragma unroll
    for (int mf = 0; mf < 2; mf++) {
      float wa = ws[(mwarp + mf * 16 + g) * 4 + h];
      float wb = ws[(mwarp + mf * 16 + g + 8) * 4 + h];
#pragma unroll
      for (int nf = 0; nf < 8; nf++) {
        acc[mf][nf][0] = fmaf(wa, fmaxf(dot[mf][nf][0], 0.f), acc[mf][nf][0]);
        acc[mf][nf][1] = fmaf(wa, fmaxf(dot[mf][nf][1], 0.f), acc[mf][nf][1]);
        acc[mf][nf][2] = fmaf(wb, fmaxf(dot[mf][nf][2], 0.f), acc[mf][nf][2]);
        acc[mf][nf][3] = fmaf(wb, fmaxf(dot[mf][nf][3], 0.f), acc[mf][nf][3]);
      }
    }
    if (h + 2 < NHEADS) {
      __syncthreads();  // all warps done with buf (h&1)
      issueA(h + 2);
      CP_COMMIT();
    }
  }

  float* obase = out + (size_t)(b * TQDIM + q0) * TKDIM + k0;
#pragma unroll
  for (int mf = 0; mf < 2; mf++) {
    int r0 = mwarp + mf * 16 + g;
#pragma unroll
    for (int nf = 0; nf < 8; nf++) {
      int col = nwarp + nf * 8 + q4 * 2;
      *(float2*)&obase[(size_t)r0 * TKDIM + col] =
          make_float2(acc[mf][nf][0], acc[mf][nf][1]);
      *(float2*)&obase[(size_t)(r0 + 8) * TKDIM + col] =
          make_float2(acc[mf][nf][2], acc[mf][nf][3]);
    }
  }
}

// ---------------------------------------------------------------------------
extern "C" void kernel_launch(void* const* d_in, const int* in_sizes, int n_in,
                              void* d_out, int out_size) {
  const float* x_q = (const float*)d_in[0];
  const float* x_k = (const float*)d_in[1];
  const float* Wq = (const float*)d_in[2];
  const float* Ww = (const float*)d_in[3];
  const float* Wk = (const float*)d_in[4];
  float* out = (float*)d_out;

  __nv_bfloat16 *xqh, *xql, *xkh, *xkl, *qIh, *qIl, *kIh, *kIl;
  float* wI;
  cudaGetSymbolAddress((void**)&xqh, g_xqh);
  cudaGetSymbolAddress((void**)&xql, g_xql);
  cudaGetSymbolAddress((void**)&xkh, g_xkh);
  cudaGetSymbolAddress((void**)&xkl, g_xkl);
  cudaGetSymbolAddress((void**)&qIh, g_qIh);
  cudaGetSymbolAddress((void**)&qIl, g_qIl);
  cudaGetSymbolAddress((void**)&kIh, g_kIh);
  cudaGetSymbolAddress((void**)&kIl, g_kIl);
  cudaGetSymbolAddress((void**)&wI, g_wI);

  cudaFuncSetAttribute(proj_kernel, cudaFuncAttributeMaxDynamicSharedMemorySize,
                       PROJ_SMEM);
  cudaFuncSetAttribute(main_mma_kernel,
                       cudaFuncAttributeMaxDynamicSharedMemorySize, MAIN_SMEM);

  const int n4 = ROWS * DMODEL / 4;
  __nv_bfloat16 *Wth, *Wtl;
  cudaGetSymbolAddress((void**)&Wth, g_Wth);
  cudaGetSymbolAddress((void**)&Wtl, g_Wtl);

  convert_kernel<<<n4 / 256, 256>>>(x_q, xqh, xql, n4);
  convert_kernel<<<n4 / 256, 256>>>(x_k, xkh, xkl, n4);
  wt_kernel<<<dim3(DMODEL / 256, 320), 256>>>(Wq, Wk, Wth, Wtl);
  proj_kernel<<<320, 256, PROJ_SMEM>>>(qIh, qIl, kIh, kIl);
  wproj_kernel<<<2048, 128>>>(x_q, Ww, wI);
  main_mma_kernel<<<dim3(TKDIM / 128, TQDIM / 128, 2), 256, MAIN_SMEM>>>(wI,
                                                                         out);
}

// round 8
// speedup vs baseline: 1.4482x; 1.0794x over previous
#include <cuda_runtime.h>
#include <cuda_bf16.h>
#include <cstdint>

// Shapes (fixed)
#define TQDIM 4096
#define TKDIM 4096
#define DMODEL 2048
#define NHEADS 4
#define ROWS 8192  // B*T

// Pre-split inputs (hi/lo bf16)
__device__ __nv_bfloat16 g_xqh[ROWS * DMODEL];
__device__ __nv_bfloat16 g_xql[ROWS * DMODEL];
__device__ __nv_bfloat16 g_xkh[ROWS * DMODEL];
__device__ __nv_bfloat16 g_xkl[ROWS * DMODEL];
__device__ __nv_bfloat16 g_Wth[320 * DMODEL];  // [n][k]; n<256: Wq col, n>=256: Wk col
__device__ __nv_bfloat16 g_Wtl[320 * DMODEL];
// Projection outputs (hi/lo bf16); q head-major [h][row][64]
__device__ __nv_bfloat16 g_qIh[NHEADS * ROWS * 64];
__device__ __nv_bfloat16 g_qIl[NHEADS * ROWS * 64];
__device__ __nv_bfloat16 g_kIh[ROWS * 64];
__device__ __nv_bfloat16 g_kIl[ROWS * 64];
__device__ float g_wI[ROWS * 4];

// ---------------------------------------------------------------------------
// helpers
// ---------------------------------------------------------------------------
__device__ __forceinline__ void split1(float v, __nv_bfloat16& h,
                                       __nv_bfloat16& l) {
  h = __float2bfloat16(v);
  l = __float2bfloat16(v - __bfloat162float(h));
}
__device__ __forceinline__ uint32_t pack2(__nv_bfloat16 a, __nv_bfloat16 b) {
  return (uint32_t)__bfloat16_as_ushort(a) |
         ((uint32_t)__bfloat16_as_ushort(b) << 16);
}
__device__ __forceinline__ void split_f4(float4 v, uint2& hi, uint2& lo) {
  __nv_bfloat16 h0, l0, h1, l1, h2, l2, h3, l3;
  split1(v.x, h0, l0); split1(v.y, h1, l1);
  split1(v.z, h2, l2); split1(v.w, h3, l3);
  hi.x = pack2(h0, h1); hi.y = pack2(h2, h3);
  lo.x = pack2(l0, l1); lo.y = pack2(l2, l3);
}

__device__ __forceinline__ void mma_bf16(float* c, const uint32_t* a,
                                         uint32_t b0, uint32_t b1) {
  asm volatile(
      "mma.sync.aligned.m16n8k16.row.col.f32.bf16.bf16.f32 "
      "{%0,%1,%2,%3}, {%4,%5,%6,%7}, {%8,%9}, {%0,%1,%2,%3};\n"
      : "+f"(c[0]), "+f"(c[1]), "+f"(c[2]), "+f"(c[3])
      : "r"(a[0]), "r"(a[1]), "r"(a[2]), "r"(a[3]), "r"(b0), "r"(b1));
}

__device__ __forceinline__ void ldmx4(uint32_t* r, const void* p) {
  uint32_t a = (uint32_t)__cvta_generic_to_shared(p);
  asm volatile(
      "ldmatrix.sync.aligned.m8n8.x4.shared.b16 {%0,%1,%2,%3}, [%4];"
      : "=r"(r[0]), "=r"(r[1]), "=r"(r[2]), "=r"(r[3])
      : "r"(a));
}

__device__ __forceinline__ void cp16(void* dst, const void* src) {
  uint32_t d = (uint32_t)__cvta_generic_to_shared(dst);
  asm volatile("cp.async.cg.shared.global [%0], [%1], 16;" :: "r"(d), "l"(src));
}
#define CP_COMMIT() asm volatile("cp.async.commit_group;" ::: "memory")
#define CP_WAIT(n) asm volatile("cp.async.wait_group %0;" :: "n"(n) : "memory")

// ---------------------------------------------------------------------------
// x_q convert (hi/lo split) fused with w_I = x_q @ Ww. One warp per row.
// ---------------------------------------------------------------------------
__global__ __launch_bounds__(256) void convq_kernel(
    const float* __restrict__ x, const float* __restrict__ Ww,
    __nv_bfloat16* __restrict__ xh, __nv_bfloat16* __restrict__ xl,
    float* __restrict__ wI) {
  int row = blockIdx.x * 8 + (threadIdx.x >> 5);
  int lane = threadIdx.x & 31;
  const float4* xr = (const float4*)(x + (size_t)row * DMODEL);
  uint2* oh = (uint2*)(xh + (size_t)row * DMODEL);
  uint2* ol = (uint2*)(xl + (size_t)row * DMODEL);
  float a0 = 0.f, a1 = 0.f, a2 = 0.f, a3 = 0.f;
#pragma unroll
  for (int i = 0; i < 16; i++) {
    int d4 = lane + i * 32;
    float4 v = xr[d4];
    uint2 hi, lo;
    split_f4(v, hi, lo);
    oh[d4] = hi;
    ol[d4] = lo;
    int d = d4 * 4;
    float4 w;
    w = *(const float4*)&Ww[(d + 0) * 4];
    a0 = fmaf(v.x, w.x, a0); a1 = fmaf(v.x, w.y, a1);
    a2 = fmaf(v.x, w.z, a2); a3 = fmaf(v.x, w.w, a3);
    w = *(const float4*)&Ww[(d + 1) * 4];
    a0 = fmaf(v.y, w.x, a0); a1 = fmaf(v.y, w.y, a1);
    a2 = fmaf(v.y, w.z, a2); a3 = fmaf(v.y, w.w, a3);
    w = *(const float4*)&Ww[(d + 2) * 4];
    a0 = fmaf(v.z, w.x, a0); a1 = fmaf(v.z, w.y, a1);
    a2 = fmaf(v.z, w.z, a2); a3 = fmaf(v.z, w.w, a3);
    w = *(const float4*)&Ww[(d + 3) * 4];
    a0 = fmaf(v.w, w.x, a0); a1 = fmaf(v.w, w.y, a1);
    a2 = fmaf(v.w, w.z, a2); a3 = fmaf(v.w, w.w, a3);
  }
#pragma unroll
  for (int off = 16; off; off >>= 1) {
    a0 += __shfl_down_sync(0xffffffffu, a0, off);
    a1 += __shfl_down_sync(0xffffffffu, a1, off);
    a2 += __shfl_down_sync(0xffffffffu, a2, off);
    a3 += __shfl_down_sync(0xffffffffu, a3, off);
  }
  if (lane == 0) *(float4*)&wI[(size_t)row * 4] = make_float4(a0, a1, a2, a3);
}

__global__ __launch_bounds__(256) void convert_kernel(
    const float* __restrict__ x, __nv_bfloat16* __restrict__ xh,
    __nv_bfloat16* __restrict__ xl, int n4) {
  int i = blockIdx.x * blockDim.x + threadIdx.x;
  if (i < n4) {
    float4 v = ((const float4*)x)[i];
    uint2 hi, lo;
    split_f4(v, hi, lo);
    ((uint2*)xh)[i] = hi;
    ((uint2*)xl)[i] = lo;
  }
}

// W transpose+split: Wt[n][k] = W[k][n]
__global__ __launch_bounds__(256) void wt_kernel(
    const float* __restrict__ Wq, const float* __restrict__ Wk,
    __nv_bfloat16* __restrict__ Wth, __nv_bfloat16* __restrict__ Wtl) {
  int k = blockIdx.x * 256 + threadIdx.x;
  int n = blockIdx.y;
  float v = (n < 256) ? Wq[(size_t)k * 256 + n] : Wk[(size_t)k * 64 + (n - 256)];
  __nv_bfloat16 h, l;
  split1(v, h, l);
  Wth[(size_t)n * DMODEL + k] = h;
  Wtl[(size_t)n * DMODEL + k] = l;
}

// ---------------------------------------------------------------------------
// Projection: C = A @ Wt^T (pre-split bf16), bf16x3 HMMA.
// CTA 128 x NT (NT=128 q / NT=64 k), 8 warps, warp 32 x NT/2.
// K-chunk 32, 2-stage cp.async, 2 CTAs/SM.
// ---------------------------------------------------------------------------
#define PSP 40                 // padded stride (halves); 80 B/row
#define PSUB (128 * 80)        // 10240 B per subtile
#define PSTG (4 * PSUB)        // 40960: Ah, Al, Bh, Bl
#define PROJ_SMEM (2 * PSTG)   // 81920

template <int NT>
__device__ __forceinline__ void proj_body(
    const __nv_bfloat16* __restrict__ Ahs, const __nv_bfloat16* __restrict__ Als,
    int m0, int nb) {
  extern __shared__ __align__(16) char smem[];
  const int tid = threadIdx.x, wid = tid >> 5, lane = tid & 31;
  const int g = lane >> 2, q4 = lane & 3;
  const int mwarp = (wid >> 1) * 32;
  const int nwarp = (wid & 1) * (NT / 2);
  const int NP = NT / 32;   // 16-row B groups per warp
  const int NF = NT / 16;   // 8-col n fragments per warp

  const int aRow = (lane & 7) + (lane & 8);
  const int aCol = (lane & 16) ? 8 : 0;
  const int bRow = (lane & 7) + ((lane & 16) ? 8 : 0);
  const int bCol = (lane & 8) ? 8 : 0;

  auto issue = [&](int kc) {
    char* st = smem + (kc & 1) * PSTG;
#pragma unroll
    for (int l = 0; l < 2; l++) {
      int idx = tid + l * 256, m = idx >> 2, c = idx & 3;
      size_t src = (size_t)(m0 + m) * DMODEL + kc * 32 + c * 8;
      cp16(st + m * 80 + c * 16, Ahs + src);
      cp16(st + PSUB + m * 80 + c * 16, Als + src);
    }
#pragma unroll
    for (int l = 0; l < NT / 64; l++) {
      int idx = tid + l * 256, n = idx >> 2, c = idx & 3;
      size_t src = (size_t)(nb + n) * DMODEL + kc * 32 + c * 8;
      cp16(st + 2 * PSUB + n * 80 + c * 16, g_Wth + src);
      cp16(st + 3 * PSUB + n * 80 + c * 16, g_Wtl + src);
    }
    CP_COMMIT();
  };

  issue(0);
  issue(1);

  float dot[2][NF][4] = {};
  const int NKC = DMODEL / 32;  // 64

  for (int kc = 0; kc < NKC; kc++) {
    if (kc + 1 < NKC) { CP_WAIT(1); } else { CP_WAIT(0); }
    __syncthreads();
    const char* st = smem + (kc & 1) * PSTG;
    const __nv_bfloat16* Ah = (const __nv_bfloat16*)st;
    const __nv_bfloat16* Al = (const __nv_bfloat16*)(st + PSUB);
    const __nv_bfloat16* Bh = (const __nv_bfloat16*)(st + 2 * PSUB);
    const __nv_bfloat16* Bl = (const __nv_bfloat16*)(st + 3 * PSUB);

#pragma unroll
    for (int ks = 0; ks < 2; ks++) {
      uint32_t ah[2][4], al[2][4];
#pragma unroll
      for (int mf = 0; mf < 2; mf++) {
        ldmx4(ah[mf], Ah + (mwarp + mf * 16 + aRow) * PSP + ks * 16 + aCol);
        ldmx4(al[mf], Al + (mwarp + mf * 16 + aRow) * PSP + ks * 16 + aCol);
      }
#pragma unroll
      for (int p = 0; p < NP; p++) {
        uint32_t bh[4], bl[4];
        ldmx4(bh, Bh + (nwarp + p * 16 + bRow) * PSP + ks * 16 + bCol);
        ldmx4(bl, Bl + (nwarp + p * 16 + bRow) * PSP + ks * 16 + bCol);
#pragma unroll
        for (int mf = 0; mf < 2; mf++) {
          mma_bf16(dot[mf][2 * p], ah[mf], bh[0], bh[1]);
          mma_bf16(dot[mf][2 * p], ah[mf], bl[0], bl[1]);
          mma_bf16(dot[mf][2 * p], al[mf], bh[0], bh[1]);
          mma_bf16(dot[mf][2 * p + 1], ah[mf], bh[2], bh[3]);
          mma_bf16(dot[mf][2 * p + 1], ah[mf], bl[2], bl[3]);
          mma_bf16(dot[mf][2 * p + 1], al[mf], bh[2], bh[3]);
        }
      }
    }
    __syncthreads();
    if (kc + 2 < NKC) issue(kc + 2);
  }

  // epilogue: split to hi/lo bf16 and write (nf covers warp's NT/2 cols only)
#pragma unroll
  for (int mf = 0; mf < 2; mf++) {
#pragma unroll
    for (int nf = 0; nf < NF; nf++) {
      int grow = m0 + mwarp + mf * 16 + g;
      __nv_bfloat16 h0, l0, h1, l1;
      if (NT == 128) {
        int ncol = nb + nwarp + nf * 8 + q4 * 2;  // q: global Wq col
        int head = ncol >> 6, hcol = ncol & 63;
        __nv_bfloat16* Oh = g_qIh + ((size_t)head * ROWS + grow) * 64 + hcol;
        __nv_bfloat16* Ol = g_qIl + ((size_t)head * ROWS + grow) * 64 + hcol;
        split1(dot[mf][nf][0], h0, l0);
        split1(dot[mf][nf][1], h1, l1);
        *(uint32_t*)Oh = pack2(h0, h1);
        *(uint32_t*)Ol = pack2(l0, l1);
        split1(dot[mf][nf][2], h0, l0);
        split1(dot[mf][nf][3], h1, l1);
        *(uint32_t*)(Oh + 8 * 64) = pack2(h0, h1);
        *(uint32_t*)(Ol + 8 * 64) = pack2(l0, l1);
      } else {
        int ncol = nwarp + nf * 8 + q4 * 2;
        __nv_bfloat16* Oh = g_kIh + (size_t)grow * 64 + ncol;
        __nv_bfloat16* Ol = g_kIl + (size_t)grow * 64 + ncol;
        split1(dot[mf][nf][0], h0, l0);
        split1(dot[mf][nf][1], h1, l1);
        *(uint32_t*)Oh = pack2(h0, h1);
        *(uint32_t*)Ol = pack2(l0, l1);
        split1(dot[mf][nf][2], h0, l0);
        split1(dot[mf][nf][3], h1, l1);
        *(uint32_t*)(Oh + 8 * 64) = pack2(h0, h1);
        *(uint32_t*)(Ol + 8 * 64) = pack2(l0, l1);
      }
    }
  }
}

__global__ __launch_bounds__(256, 2) void proj_kernel() {
  const int bx = blockIdx.x;
  if (bx < 128) {
    proj_body<128>(g_xqh, g_xql, (bx >> 1) * 128, (bx & 1) * 128);
  } else {
    proj_body<64>(g_xkh, g_xkl, (bx - 128) * 128, 256);
  }
}

// ---------------------------------------------------------------------------
// Main: CTA 128q x 64k, 8 warps (4x2), warp 32x32, 2 CTAs/SM.
// A (q head) hi/lo double-buffered cp.async; B (k) fixed; per head:
// dot (bf16x3) -> relu -> w-weighted accumulate.
// ---------------------------------------------------------------------------
#define MSP 72
#define MAB (128 * MSP * 2)                 // 18432
#define MBB (64 * MSP * 2)                  // 9216
#define M_B (4 * MAB)
#define M_WS (4 * MAB + 2 * MBB)
#define MAIN_SMEM (4 * MAB + 2 * MBB + 2048)  // 94208

__global__ __launch_bounds__(256, 2) void main_mma_kernel(
    const float* __restrict__ wI, float* __restrict__ out) {
  extern __shared__ __align__(16) char smem[];
  float* ws = (float*)(smem + M_WS);

  const int tid = threadIdx.x, wid = tid >> 5, lane = tid & 31;
  const int g = lane >> 2, q4 = lane & 3;
  const int mwarp = (wid >> 1) * 32, nwarp = (wid & 1) * 32;
  const int b = blockIdx.z, q0 = blockIdx.y * 128, k0 = blockIdx.x * 64;

  const int aRow = (lane & 7) + (lane & 8);
  const int aCol = (lane & 16) ? 8 : 0;
  const int bRow = (lane & 7) + ((lane & 16) ? 8 : 0);
  const int bCol = (lane & 8) ? 8 : 0;

  auto issueA = [&](int h) {
    char* st = smem + (h & 1) * 2 * MAB;
    size_t base = ((size_t)h * ROWS + b * TQDIM + q0) * 64;
#pragma unroll
    for (int l = 0; l < 4; l++) {
      int idx = tid + l * 256, m = idx >> 3, c = idx & 7;
      cp16(st + m * 144 + c * 16, g_qIh + base + (size_t)m * 64 + c * 8);
      cp16(st + MAB + m * 144 + c * 16, g_qIl + base + (size_t)m * 64 + c * 8);
    }
  };

  // prologue: group0 = B + A(0); group1 = A(1)
  {
    char* st = smem + M_B;
    size_t base = ((size_t)b * TKDIM + k0) * 64;
#pragma unroll
    for (int l = 0; l < 2; l++) {
      int idx = tid + l * 256, m = idx >> 3, c = idx & 7;
      cp16(st + m * 144 + c * 16, g_kIh + base + (size_t)m * 64 + c * 8);
      cp16(st + MBB + m * 144 + c * 16, g_kIl + base + (size_t)m * 64 + c * 8);
    }
  }
  issueA(0);
  CP_COMMIT();
  issueA(1);
  CP_COMMIT();
  if (tid < 128)
    *(float4*)&ws[tid * 4] =
        *(const float4*)&wI[(size_t)(b * TQDIM + q0 + tid) * 4];

  const __nv_bfloat16* Bh = (const __nv_bfloat16*)(smem + M_B);
  const __nv_bfloat16* Bl = (const __nv_bfloat16*)(smem + M_B + MBB);

  float acc[2][4][4] = {};

  for (int h = 0; h < NHEADS; h++) {
    if (h + 1 < NHEADS) { CP_WAIT(1); } else { CP_WAIT(0); }
    __syncthreads();
    const __nv_bfloat16* Ah = (const __nv_bfloat16*)(smem + (h & 1) * 2 * MAB);
    const __nv_bfloat16* Al = (const __nv_bfloat16*)((const char*)Ah + MAB);

    float dot[2][4][4] = {};
#pragma unroll
    for (int ks = 0; ks < 4; ks++) {
      uint32_t ah[2][4], al[2][4];
#pragma unroll
      for (int mf = 0; mf < 2; mf++) {
        ldmx4(ah[mf], Ah + (mwarp + mf * 16 + aRow) * MSP + ks * 16 + aCol);
        ldmx4(al[mf], Al + (mwarp + mf * 16 + aRow) * MSP + ks * 16 + aCol);
      }
#pragma unroll
      for (int p = 0; p < 2; p++) {
        uint32_t bh[4], bl[4];
        ldmx4(bh, Bh + (nwarp + p * 16 + bRow) * MSP + ks * 16 + bCol);
        ldmx4(bl, Bl + (nwarp + p * 16 + bRow) * MSP + ks * 16 + bCol);
#pragma unroll
        for (int mf = 0; mf < 2; mf++) {
          mma_bf16(dot[mf][2 * p], ah[mf], bh[0], bh[1]);
          mma_bf16(dot[mf][2 * p], ah[mf], bl[0], bl[1]);
          mma_bf16(dot[mf][2 * p], al[mf], bh[0], bh[1]);
          mma_bf16(dot[mf][2 * p + 1], ah[mf], bh[2], bh[3]);
          mma_bf16(dot[mf][2 * p + 1], ah[mf], bl[2], bl[3]);
          mma_bf16(dot[mf][2 * p + 1], al[mf], bh[2], bh[3]);
        }
      }
    }
    // relu + weighted accumulate
#pragma unroll
    for (int mf = 0; mf < 2; mf++) {
      float wa = ws[(mwarp + mf * 16 + g) * 4 + h];
      float wb = ws[(mwarp + mf * 16 + g + 8) * 4 + h];
#pragma unroll
      for (int nf = 0; nf < 4; nf++) {
        acc[mf][nf][0] = fmaf(wa, fmaxf(dot[mf][nf][0], 0.f), acc[mf][nf][0]);
        acc[mf][nf][1] = fmaf(wa, fmaxf(dot[mf][nf][1], 0.f), acc[mf][nf][1]);
        acc[mf][nf][2] = fmaf(wb, fmaxf(dot[mf][nf][2], 0.f), acc[mf][nf][2]);
        acc[mf][nf][3] = fmaf(wb, fmaxf(dot[mf][nf][3], 0.f), acc[mf][nf][3]);
      }
    }
    if (h + 2 < NHEADS) {
      __syncthreads();  // all warps done with buf (h&1)
      issueA(h + 2);
      CP_COMMIT();
    }
  }

  float* obase = out + (size_t)(b * TQDIM + q0) * TKDIM + k0;
#pragma unroll
  for (int mf = 0; mf < 2; mf++) {
    int r0 = mwarp + mf * 16 + g;
#pragma unroll
    for (int nf = 0; nf < 4; nf++) {
      int col = nwarp + nf * 8 + q4 * 2;
      *(float2*)&obase[(size_t)r0 * TKDIM + col] =
          make_float2(acc[mf][nf][0], acc[mf][nf][1]);
      *(float2*)&obase[(size_t)(r0 + 8) * TKDIM + col] =
          make_float2(acc[mf][nf][2], acc[mf][nf][3]);
    }
  }
}

// ---------------------------------------------------------------------------
extern "C" void kernel_launch(void* const* d_in, const int* in_sizes, int n_in,
                              void* d_out, int out_size) {
  const float* x_q = (const float*)d_in[0];
  const float* x_k = (const float*)d_in[1];
  const float* Wq = (const float*)d_in[2];
  const float* Ww = (const float*)d_in[3];
  const float* Wk = (const float*)d_in[4];
  float* out = (float*)d_out;

  __nv_bfloat16 *xqh, *xql, *xkh, *xkl, *Wth, *Wtl;
  float* wI;
  cudaGetSymbolAddress((void**)&xqh, g_xqh);
  cudaGetSymbolAddress((void**)&xql, g_xql);
  cudaGetSymbolAddress((void**)&xkh, g_xkh);
  cudaGetSymbolAddress((void**)&xkl, g_xkl);
  cudaGetSymbolAddress((void**)&Wth, g_Wth);
  cudaGetSymbolAddress((void**)&Wtl, g_Wtl);
  cudaGetSymbolAddress((void**)&wI, g_wI);

  cudaFuncSetAttribute(proj_kernel, cudaFuncAttributeMaxDynamicSharedMemorySize,
                       PROJ_SMEM);
  cudaFuncSetAttribute(main_mma_kernel,
                       cudaFuncAttributeMaxDynamicSharedMemorySize, MAIN_SMEM);

  const int n4 = ROWS * DMODEL / 4;
  convq_kernel<<<ROWS / 8, 256>>>(x_q, Ww, xqh, xql, wI);
  convert_kernel<<<n4 / 256, 256>>>(x_k, xkh, xkl, n4);
  wt_kernel<<<dim3(DMODEL / 256, 320), 256>>>(Wq, Wk, Wth, Wtl);
  proj_kernel<<<192, 256, PROJ_SMEM>>>();
  main_mma_kernel<<<dim3(TKDIM / 64, TQDIM / 128, 2), 256, MAIN_SMEM>>>(wI,
                                                                        out);
}